// round 11
// baseline (speedup 1.0000x reference)
#include <cuda_runtime.h>
#include <math.h>

#define B        512
#define IN       1024
#define NN       4224
#define TOTAL    5248
#define KB       128
#define NBLK     33
#define OUT_N    128
#define SC       2.8853900817779268f   // 2*log2(e)

// Device-global scratch (allocation-free rule). All buffers are either
// overwritten every run or zeroed before accumulation -> replay-safe.
__device__ float g_ph  [(size_t)4 * B * NN];          // split-K preA partials
__device__ float g_upd [(size_t)B * NN];              // far-update accumulator
__device__ float g_hall[(size_t)B * NN];              // published h per node
__device__ float g_nacc[(size_t)B * NN];              // near contribution (overwrite)
__device__ float g_tri [(size_t)NBLK * KB * KB];      // [b][t][i] scaled, zeroed t>=i
__device__ float g_nw  [(size_t)(NBLK - 1) * KB * KB];// [b][t][n] next-block weights

// ---------------------------------------------------------------------------
// GEMM core (validated R6/R8 form: FFMA2 + pack movs, single-buffered smem).
// C[r][cjbase+n] (+)= sum_k A[r][aoff+k] * Wsub[n*TOTAL + k];  C row stride NN.
// ---------------------------------------------------------------------------
#define BM 128
#define BN 64
#define BK 16
#define AS 132
#define BS 68

__device__ __forceinline__ void
gemm_core(const float* __restrict__ A, int lda, int aoff,
          const float* __restrict__ Wsub, float* __restrict__ C,
          int cjbase, int kc, bool accum, float* As_, float* Bs_)
{
    int m0 = blockIdx.x * BM;
    int n0 = blockIdx.y * BN;
    int tid = threadIdx.x;
    int tx = tid & 15;
    int ty = tid >> 4;

    int a_r = tid >> 1;
    int a_k = (tid & 1) * 8;
    int b_r = tid >> 2;
    int b_k = (tid & 3) * 4;

    unsigned long long acc2[4][4];
#pragma unroll
    for (int i = 0; i < 4; i++)
#pragma unroll
        for (int j = 0; j < 4; j++) acc2[i][j] = 0ull;

    for (int kk = 0; kk < kc; kk += BK) {
        float4 a0 = *(const float4*)(A + (size_t)(m0 + a_r) * lda + aoff + kk + a_k);
        float4 a1 = *(const float4*)(A + (size_t)(m0 + a_r) * lda + aoff + kk + a_k + 4);
        As_[(a_k + 0) * AS + a_r] = a0.x;
        As_[(a_k + 1) * AS + a_r] = a0.y;
        As_[(a_k + 2) * AS + a_r] = a0.z;
        As_[(a_k + 3) * AS + a_r] = a0.w;
        As_[(a_k + 4) * AS + a_r] = a1.x;
        As_[(a_k + 5) * AS + a_r] = a1.y;
        As_[(a_k + 6) * AS + a_r] = a1.z;
        As_[(a_k + 7) * AS + a_r] = a1.w;

        float4 bv = *(const float4*)(Wsub + (size_t)(n0 + b_r) * TOTAL + kk + b_k);
        Bs_[(b_k + 0) * BS + b_r] = bv.x;
        Bs_[(b_k + 1) * BS + b_r] = bv.y;
        Bs_[(b_k + 2) * BS + b_r] = bv.z;
        Bs_[(b_k + 3) * BS + b_r] = bv.w;

        __syncthreads();

#pragma unroll
        for (int k = 0; k < BK; k++) {
            float a[8], b[4];
            *(float4*)&a[0] = *(const float4*)&As_[k * AS + ty * 8];
            *(float4*)&a[4] = *(const float4*)&As_[k * AS + ty * 8 + 4];
            *(float4*)&b[0] = *(const float4*)&Bs_[k * BS + tx * 4];

            unsigned long long ap[4], bb[4];
#pragma unroll
            for (int i = 0; i < 4; i++)
                asm("mov.b64 %0, {%1, %2};"
                    : "=l"(ap[i]) : "f"(a[2 * i]), "f"(a[2 * i + 1]));
#pragma unroll
            for (int j = 0; j < 4; j++)
                asm("mov.b64 %0, {%1, %2};"
                    : "=l"(bb[j]) : "f"(b[j]), "f"(b[j]));

#pragma unroll
            for (int i = 0; i < 4; i++)
#pragma unroll
                for (int j = 0; j < 4; j++)
                    asm("fma.rn.f32x2 %0, %1, %2, %0;"
                        : "+l"(acc2[i][j]) : "l"(ap[i]), "l"(bb[j]));
        }
        __syncthreads();
    }

#pragma unroll
    for (int i = 0; i < 4; i++) {
        float v0[4], v1[4];
#pragma unroll
        for (int j = 0; j < 4; j++)
            asm("mov.b64 {%0, %1}, %2;"
                : "=f"(v0[j]), "=f"(v1[j]) : "l"(acc2[i][j]));

        float* c0 = C + (size_t)(m0 + ty * 8 + 2 * i) * NN + cjbase + n0 + tx * 4;
        float* c1 = c0 + NN;
        if (accum) {
#pragma unroll
            for (int j = 0; j < 4; j++) { c0[j] += v0[j]; c1[j] += v1[j]; }
        } else {
            float4 w0, w1;
            w0.x = v0[0]; w0.y = v0[1]; w0.z = v0[2]; w0.w = v0[3];
            w1.x = v1[0]; w1.y = v1[1]; w1.z = v1[2]; w1.w = v1[3];
            *(float4*)c0 = w0;
            *(float4*)c1 = w1;
        }
    }
}

// preA split-K: g_ph[z][:, n] = x[:, z*256:(z+1)*256] @ W[n, z*256:...]^T.
// One launch, grid (4, 66, 4) -> full chip, no serial head.
__global__ void __launch_bounds__(256)
prea_kernel(const float* __restrict__ x, const float* __restrict__ W)
{
    __shared__ float As_[BK * AS];
    __shared__ float Bs_[BK * BS];
    int ks = blockIdx.z;
    gemm_core(x, IN, ks * 256, W + ks * 256,
              g_ph + (size_t)ks * B * NN, 0, 256, false, As_, Bs_);
}

// Far update U(b): g_upd[:, (b+2)*KB..] += h_b @ W^T. Event-ordered (no spin).
__global__ void __launch_bounds__(256)
upd_kernel(const float* __restrict__ W, int b)
{
    __shared__ float As_[BK * AS];
    __shared__ float Bs_[BK * BS];
    int jb = (b + 2) * KB;
    gemm_core(g_hall, NN, b * KB,
              W + (size_t)jb * TOTAL + IN + b * KB,
              g_upd, jb, KB, true, As_, Bs_);
}

__global__ void zero_upd_kernel()
{
    size_t i = (size_t)blockIdx.x * blockDim.x + threadIdx.x;
    ((float4*)g_upd)[i] = make_float4(0.f, 0.f, 0.f, 0.f);
}

// ---------------------------------------------------------------------------
// Prep: transpose W block tiles into compact [t][node] buffers.
//  CTA c < NBLK      : g_tri[b][t][i] = (t<i) ? W[b*128+i][IN+b*128+t]*SC : 0
//  CTA c >= NBLK     : g_nw[b][t][n]  = W[(b+1)*128+n][IN+b*128+t]
// ---------------------------------------------------------------------------
__global__ void __launch_bounds__(256)
prep_kernel(const float* __restrict__ W)
{
    __shared__ float tile[64 * 133];
    int c = blockIdx.x;
    int tid = threadIdx.x;
    bool isTri = (c < NBLK);
    int b = isTri ? c : c - NBLK;
    const float* src = isTri ? W + (size_t)(b * KB) * TOTAL + IN + b * KB
                             : W + (size_t)((b + 1) * KB) * TOTAL + IN + b * KB;
    float* dst = isTri ? g_tri + (size_t)b * KB * KB
                       : g_nw  + (size_t)b * KB * KB;

    for (int h = 0; h < 2; h++) {
        for (int l = tid; l < 64 * 128; l += 256) {
            int r = l >> 7, t = l & 127;
            int i = h * 64 + r;
            float v = src[(size_t)i * TOTAL + t];
            if (isTri) v = (t < i) ? v * SC : 0.0f;
            tile[r * 133 + t] = v;
        }
        __syncthreads();
        for (int l = tid; l < 64 * 128; l += 256) {
            int t = l >> 6, n = l & 63;
            dst[t * 128 + h * 64 + n] = tile[n * 133 + t];
        }
        __syncthreads();
    }
}

// ---------------------------------------------------------------------------
// Sequential recurrence + fused near-update. 32 CTAs x 512 thr (16 warps =
// 4 warps/SMSP: validated latency-hiding shape from R5/R6); warp = row.
// Lane owns nodes 4*lane..4*lane+3 -> fully vectorized:
//  stage: 8 x (LDG.128 + STS.128)/thread; init: float4 partial sums;
//  step t: tanh(z[t&3]) -> shfl(t>>2) -> 1x LDS.128 + 4 FMA (w zeroed t>=i).
//  near-update reads g_nw directly (coalesced LDG.128, L2-hot).
// ---------------------------------------------------------------------------
__global__ void __launch_bounds__(512, 1)
seq_kernel(float* __restrict__ out, int b)
{
    extern __shared__ float sm[];
    float* ws = sm;                 // 128*132 floats (tri tile [t][i])
    float* hs = sm + 128 * 132;     // 16*128 floats (per-row h)

    int tid  = threadIdx.x;         // 512
    int lane = tid & 31;
    int wid  = tid >> 5;            // 0..15
    int row  = blockIdx.x * 16 + wid;
    int j0   = b * KB;

    // Stage tri tile (fully vectorized, coalesced).
    {
        const float4* tsrc = (const float4*)(g_tri + (size_t)b * KB * KB);
#pragma unroll
        for (int k = 0; k < 8; k++) {
            int idx4 = tid + k * 512;          // 0..4095
            int t  = idx4 >> 5;
            int i4 = (idx4 & 31) * 4;
            *(float4*)&ws[t * 132 + i4] = tsrc[idx4];
        }
    }

    // Init z = (sum of 4 split-K partials [+ near] [+ far]) * SC.
    float z[4];
    {
        size_t o4 = ((size_t)row * NN + j0) / 4 + lane;
        const float4* p = (const float4*)g_ph;
        size_t stride4 = (size_t)B * NN / 4;
        float4 v0 = p[o4];
        float4 v1 = p[stride4 + o4];
        float4 v2 = p[2 * stride4 + o4];
        float4 v3 = p[3 * stride4 + o4];
        float4 s;
        s.x = (v0.x + v1.x) + (v2.x + v3.x);
        s.y = (v0.y + v1.y) + (v2.y + v3.y);
        s.z = (v0.z + v1.z) + (v2.z + v3.z);
        s.w = (v0.w + v1.w) + (v2.w + v3.w);
        if (b >= 1) {
            float4 nv = ((const float4*)g_nacc)[o4];
            s.x += nv.x; s.y += nv.y; s.z += nv.z; s.w += nv.w;
        }
        if (b >= 2) {
            float4 uv = ((const float4*)g_upd)[o4];
            s.x += uv.x; s.y += uv.y; s.z += uv.z; s.w += uv.w;
        }
        z[0] = s.x * SC; z[1] = s.y * SC; z[2] = s.z * SC; z[3] = s.w * SC;
    }
    __syncthreads();

    // Recurrence: 128 steps. Producer of step t is lane t>>2, component t&3.
    const float* wrow = ws + lane * 4;   // + t*132
    for (int t0 = 0; t0 < 128; t0 += 8) {
#pragma unroll
        for (int tk = 0; tk < 8; tk++) {
            int t = t0 + tk;
            float e;  asm("ex2.approx.f32 %0, %1;" : "=f"(e) : "f"(z[tk & 3]));
            float d = e + 1.0f;
            float r;  asm("rcp.approx.f32 %0, %1;" : "=f"(r) : "f"(d));
            float hv = fmaf(-2.0f, r, 1.0f);

            float h = __shfl_sync(0xffffffffu, hv, t >> 2);

            float4 w = *(const float4*)(wrow + t * 132);
            z[0] = fmaf(h, w.x, z[0]);
            z[1] = fmaf(h, w.y, z[1]);
            z[2] = fmaf(h, w.z, z[2]);
            z[3] = fmaf(h, w.w, z[3]);
        }
    }

    // Finalize own h (z[c] final after own step; later w entries are 0).
    float h4[4];
#pragma unroll
    for (int c = 0; c < 4; c++) {
        float e;  asm("ex2.approx.f32 %0, %1;" : "=f"(e) : "f"(z[c]));
        float d = e + 1.0f;
        float r;  asm("rcp.approx.f32 %0, %1;" : "=f"(r) : "f"(d));
        h4[c] = fmaf(-2.0f, r, 1.0f);
    }

    if (b == NBLK - 1) {
        float4 o;
        o.x = 1.0f / (1.0f + __expf(-h4[0]));
        o.y = 1.0f / (1.0f + __expf(-h4[1]));
        o.z = 1.0f / (1.0f + __expf(-h4[2]));
        o.w = 1.0f / (1.0f + __expf(-h4[3]));
        *(float4*)(out + (size_t)row * OUT_N + 4 * lane) = o;
        return;
    }

    // Publish h: smem for fused near-update; gmem for U(b) (event-ordered).
    *(float4*)&hs[wid * 128 + 4 * lane] = *(float4*)h4;
    if (b <= NBLK - 3)
        *(float4*)(g_hall + (size_t)row * NN + j0 + 4 * lane) = *(float4*)h4;
    __syncthreads();

    // Near-update: g_nacc[row][block b+1] = h_row @ Wn^T (overwrite).
    {
        const float4* nsrc = (const float4*)(g_nw + (size_t)b * KB * KB);
        const float* hrow = hs + wid * 128;
        float acc0 = 0.f, acc1 = 0.f, acc2 = 0.f, acc3 = 0.f;
#pragma unroll 4
        for (int t = 0; t < 128; t++) {
            float hv = hrow[t];
            float4 w = nsrc[t * 32 + lane];
            acc0 = fmaf(hv, w.x, acc0);
            acc1 = fmaf(hv, w.y, acc1);
            acc2 = fmaf(hv, w.z, acc2);
            acc3 = fmaf(hv, w.w, acc3);
        }
        float4 a; a.x = acc0; a.y = acc1; a.z = acc2; a.w = acc3;
        *(float4*)(g_nacc + (size_t)row * NN + j0 + KB + 4 * lane) = a;
    }
}

// ---------------------------------------------------------------------------
// Host: pure event ordering (NO device-side spinning anywhere).
//  s3: prep -> preA(split-K, full chip) -> evC
//  s2: zero g_upd; then U(b) after evS[b]
//  0 : wait evC; seq(b) [waits evU[b-2]]; record evS[b]
// ---------------------------------------------------------------------------
extern "C" void kernel_launch(void* const* d_in, const int* in_sizes, int n_in,
                              void* d_out, int out_size)
{
    const float* x = (const float*)d_in[0];   // [512][1024]
    const float* W = (const float*)d_in[1];   // [4224][5248]
    float* out = (float*)d_out;               // [512][128]
    (void)in_sizes; (void)n_in; (void)out_size;

    static bool inited = false;
    static cudaStream_t s2, s3;
    static cudaEvent_t evFork, evC, evE2;
    static cudaEvent_t evS[NBLK], evU[NBLK];
    if (!inited) {
        cudaStreamCreateWithFlags(&s2, cudaStreamNonBlocking);
        cudaStreamCreateWithFlags(&s3, cudaStreamNonBlocking);
        cudaEventCreateWithFlags(&evFork, cudaEventDisableTiming);
        cudaEventCreateWithFlags(&evC,    cudaEventDisableTiming);
        cudaEventCreateWithFlags(&evE2,   cudaEventDisableTiming);
        for (int i = 0; i < NBLK; i++) {
            cudaEventCreateWithFlags(&evS[i], cudaEventDisableTiming);
            cudaEventCreateWithFlags(&evU[i], cudaEventDisableTiming);
        }
        cudaFuncSetAttribute(seq_kernel,
                             cudaFuncAttributeMaxDynamicSharedMemorySize,
                             (128 * 132 + 16 * 128) * 4);
        inited = true;
    }

    cudaEventRecord(evFork, 0);
    cudaStreamWaitEvent(s2, evFork, 0);
    cudaStreamWaitEvent(s3, evFork, 0);

    // s3: prep tiles, then full split-K preA.
    prep_kernel<<<2 * NBLK - 1, 256, 0, s3>>>(W);
    prea_kernel<<<dim3(4, 66, 4), 256, 0, s3>>>(x, W);
    cudaEventRecord(evC, s3);

    // s2: zero the far accumulator (U(0) is serialized behind it).
    zero_upd_kernel<<<2112, 256, 0, s2>>>();

    // stream 0: the pipeline.
    cudaStreamWaitEvent(0, evC, 0);
    for (int b = 0; b < NBLK; b++) {
        if (b >= 2) cudaStreamWaitEvent(0, evU[b - 2], 0);

        seq_kernel<<<32, 512, (128 * 132 + 16 * 128) * 4, 0>>>(out, b);

        if (b <= NBLK - 3) {
            cudaEventRecord(evS[b], 0);
            cudaStreamWaitEvent(s2, evS[b], 0);
            int jb = (b + 2) * KB;
            upd_kernel<<<dim3(4, (NN - jb) / 64), 256, 0, s2>>>(W, b);
            cudaEventRecord(evU[b], s2);
        }
    }
    cudaEventRecord(evE2, s2);
    cudaStreamWaitEvent(0, evE2, 0);
}

// round 12
// speedup vs baseline: 1.2902x; 1.2902x over previous
#include <cuda_runtime.h>
#include <math.h>

#define B        512
#define IN       1024
#define NN       4224
#define TOTAL    5248
#define KB       128
#define NBLK     33
#define OUT_N    128
#define SC       2.8853900817779268f   // 2*log2(e)

// Device-global scratch (allocation-free rule). Replay-safe: every buffer is
// overwritten each run, or zeroed before accumulation.
__device__ float g_ph  [(size_t)4 * B * NN];          // split-K preA partials
__device__ float g_upd [(size_t)B * NN];              // far-update accumulator
__device__ float g_hall[(size_t)B * NN];              // published h per node
__device__ float g_nacc[(size_t)B * NN];              // near contribution (overwrite)
__device__ float g_tri [(size_t)NBLK * KB * KB];      // [b][t][i] scaled, zeroed t>=i
__device__ float g_nw  [(size_t)(NBLK - 1) * KB * KB];// [b][t][n] next-block weights

// ---------------------------------------------------------------------------
// GEMM core (validated R6/R8 form: FFMA2 + pack movs, single-buffered smem).
// C[r][cjbase+n] (+)= sum_k A[r][aoff+k] * Wsub[n*TOTAL + k];  C row stride NN.
// ---------------------------------------------------------------------------
#define BM 128
#define BN 64
#define BK 16
#define AS 132
#define BS 68

__device__ __forceinline__ void
gemm_core(const float* __restrict__ A, int lda, int aoff,
          const float* __restrict__ Wsub, float* __restrict__ C,
          int cjbase, int kc, bool accum, float* As_, float* Bs_)
{
    int m0 = blockIdx.x * BM;
    int n0 = blockIdx.y * BN;
    int tid = threadIdx.x;
    int tx = tid & 15;
    int ty = tid >> 4;

    int a_r = tid >> 1;
    int a_k = (tid & 1) * 8;
    int b_r = tid >> 2;
    int b_k = (tid & 3) * 4;

    unsigned long long acc2[4][4];
#pragma unroll
    for (int i = 0; i < 4; i++)
#pragma unroll
        for (int j = 0; j < 4; j++) acc2[i][j] = 0ull;

    for (int kk = 0; kk < kc; kk += BK) {
        float4 a0 = *(const float4*)(A + (size_t)(m0 + a_r) * lda + aoff + kk + a_k);
        float4 a1 = *(const float4*)(A + (size_t)(m0 + a_r) * lda + aoff + kk + a_k + 4);
        As_[(a_k + 0) * AS + a_r] = a0.x;
        As_[(a_k + 1) * AS + a_r] = a0.y;
        As_[(a_k + 2) * AS + a_r] = a0.z;
        As_[(a_k + 3) * AS + a_r] = a0.w;
        As_[(a_k + 4) * AS + a_r] = a1.x;
        As_[(a_k + 5) * AS + a_r] = a1.y;
        As_[(a_k + 6) * AS + a_r] = a1.z;
        As_[(a_k + 7) * AS + a_r] = a1.w;

        float4 bv = *(const float4*)(Wsub + (size_t)(n0 + b_r) * TOTAL + kk + b_k);
        Bs_[(b_k + 0) * BS + b_r] = bv.x;
        Bs_[(b_k + 1) * BS + b_r] = bv.y;
        Bs_[(b_k + 2) * BS + b_r] = bv.z;
        Bs_[(b_k + 3) * BS + b_r] = bv.w;

        __syncthreads();

#pragma unroll
        for (int k = 0; k < BK; k++) {
            float a[8], b[4];
            *(float4*)&a[0] = *(const float4*)&As_[k * AS + ty * 8];
            *(float4*)&a[4] = *(const float4*)&As_[k * AS + ty * 8 + 4];
            *(float4*)&b[0] = *(const float4*)&Bs_[k * BS + tx * 4];

            unsigned long long ap[4], bb[4];
#pragma unroll
            for (int i = 0; i < 4; i++)
                asm("mov.b64 %0, {%1, %2};"
                    : "=l"(ap[i]) : "f"(a[2 * i]), "f"(a[2 * i + 1]));
#pragma unroll
            for (int j = 0; j < 4; j++)
                asm("mov.b64 %0, {%1, %2};"
                    : "=l"(bb[j]) : "f"(b[j]), "f"(b[j]));

#pragma unroll
            for (int i = 0; i < 4; i++)
#pragma unroll
                for (int j = 0; j < 4; j++)
                    asm("fma.rn.f32x2 %0, %1, %2, %0;"
                        : "+l"(acc2[i][j]) : "l"(ap[i]), "l"(bb[j]));
        }
        __syncthreads();
    }

#pragma unroll
    for (int i = 0; i < 4; i++) {
        float v0[4], v1[4];
#pragma unroll
        for (int j = 0; j < 4; j++)
            asm("mov.b64 {%0, %1}, %2;"
                : "=f"(v0[j]), "=f"(v1[j]) : "l"(acc2[i][j]));

        float* c0 = C + (size_t)(m0 + ty * 8 + 2 * i) * NN + cjbase + n0 + tx * 4;
        float* c1 = c0 + NN;
        if (accum) {
#pragma unroll
            for (int j = 0; j < 4; j++) { c0[j] += v0[j]; c1[j] += v1[j]; }
        } else {
            float4 w0, w1;
            w0.x = v0[0]; w0.y = v0[1]; w0.z = v0[2]; w0.w = v0[3];
            w1.x = v1[0]; w1.y = v1[1]; w1.z = v1[2]; w1.w = v1[3];
            *(float4*)c0 = w0;
            *(float4*)c1 = w1;
        }
    }
}

// preA split-K, CHUNKED over node columns: chunk covers BN-columns
// [y0*64, (y0+gridDim.y)*64). g_ph[z] = x[:, z*256:...] @ W[cols, z*256:...]^T
__global__ void __launch_bounds__(256)
prea_kernel(const float* __restrict__ x, const float* __restrict__ W, int y0)
{
    __shared__ float As_[BK * AS];
    __shared__ float Bs_[BK * BS];
    int ks = blockIdx.z;
    gemm_core(x, IN, ks * 256,
              W + (size_t)y0 * 64 * TOTAL + ks * 256,
              g_ph + (size_t)ks * B * NN, y0 * 64, 256, false, As_, Bs_);
}

// Far update U(b): g_upd[:, (b+2)*KB..] += h_b @ W^T. Event-ordered (no spin).
__global__ void __launch_bounds__(256)
upd_kernel(const float* __restrict__ W, int b)
{
    __shared__ float As_[BK * AS];
    __shared__ float Bs_[BK * BS];
    int jb = (b + 2) * KB;
    gemm_core(g_hall, NN, b * KB,
              W + (size_t)jb * TOTAL + IN + b * KB,
              g_upd, jb, KB, true, As_, Bs_);
}

__global__ void zero_upd_kernel()
{
    size_t i = (size_t)blockIdx.x * blockDim.x + threadIdx.x;
    ((float4*)g_upd)[i] = make_float4(0.f, 0.f, 0.f, 0.f);
}

// ---------------------------------------------------------------------------
// Prep: transpose W block tiles into compact [t][node] buffers.
//  CTA c < NBLK : g_tri[b][t][i] = (t<i) ? W[b*128+i][IN+b*128+t]*SC : 0
//  CTA c >= NBLK: g_nw[b][t][n]  = W[(b+1)*128+n][IN+b*128+t]
// ---------------------------------------------------------------------------
__global__ void __launch_bounds__(256)
prep_kernel(const float* __restrict__ W)
{
    __shared__ float tile[64 * 133];
    int c = blockIdx.x;
    int tid = threadIdx.x;
    bool isTri = (c < NBLK);
    int b = isTri ? c : c - NBLK;
    const float* src = isTri ? W + (size_t)(b * KB) * TOTAL + IN + b * KB
                             : W + (size_t)((b + 1) * KB) * TOTAL + IN + b * KB;
    float* dst = isTri ? g_tri + (size_t)b * KB * KB
                       : g_nw  + (size_t)b * KB * KB;

    for (int h = 0; h < 2; h++) {
        for (int l = tid; l < 64 * 128; l += 256) {
            int r = l >> 7, t = l & 127;
            int i = h * 64 + r;
            float v = src[(size_t)i * TOTAL + t];
            if (isTri) v = (t < i) ? v * SC : 0.0f;
            tile[r * 133 + t] = v;
        }
        __syncthreads();
        for (int l = tid; l < 64 * 128; l += 256) {
            int t = l >> 6, n = l & 63;
            dst[t * 128 + h * 64 + n] = tile[n * 133 + t];
        }
        __syncthreads();
    }
}

// ---------------------------------------------------------------------------
// Sequential recurrence + fused near-update. 32 CTAs x 512 thr (16 warps = 4
// warps/SMSP, the validated latency-hiding shape); warp = batch row; lane owns
// nodes 4*lane..4*lane+3.
//  - BOTH tiles (tri + near) staged into smem up front (float4, coalesced).
//  - Recurrence step: EXPLICIT next-w prefetch (LDS off the chain), then
//    EX2 -> FADD -> RCP -> FMA -> SHFL -> 4x FMA.   chain ~88 cyc/step.
//  - Near-update runs entirely from smem.
// smem: ws 128*132 | nearw 128*128 | hs 16*128   = 141312 B (1 CTA/SM).
// ---------------------------------------------------------------------------
__global__ void __launch_bounds__(512, 1)
seq_kernel(float* __restrict__ out, int b)
{
    extern __shared__ float sm[];
    float* ws    = sm;                       // tri tile [t][i], stride 132
    float* nearw = sm + 128 * 132;           // near tile [t][n], stride 128
    float* hs    = sm + 128 * 132 + 128 * 128;  // per-row h

    int tid  = threadIdx.x;         // 512
    int lane = tid & 31;
    int wid  = tid >> 5;            // 0..15
    int row  = blockIdx.x * 16 + wid;
    int j0   = b * KB;

    // Stage tri tile (and near tile when it exists), fully vectorized.
    {
        const float4* tsrc = (const float4*)(g_tri + (size_t)b * KB * KB);
#pragma unroll
        for (int k = 0; k < 8; k++) {
            int idx4 = tid + k * 512;          // 0..4095
            int t  = idx4 >> 5;
            int i4 = (idx4 & 31) * 4;
            *(float4*)&ws[t * 132 + i4] = tsrc[idx4];
        }
        if (b < NBLK - 1) {
            const float4* nsrc = (const float4*)(g_nw + (size_t)b * KB * KB);
#pragma unroll
            for (int k = 0; k < 8; k++) {
                int idx4 = tid + k * 512;
                *(float4*)&nearw[idx4 * 4] = nsrc[idx4];
            }
        }
    }

    // Init z = (sum of 4 split-K partials [+ near] [+ far]) * SC.
    float z[4];
    {
        size_t o4 = ((size_t)row * NN + j0) / 4 + lane;
        const float4* p = (const float4*)g_ph;
        size_t stride4 = (size_t)B * NN / 4;
        float4 v0 = p[o4];
        float4 v1 = p[stride4 + o4];
        float4 v2 = p[2 * stride4 + o4];
        float4 v3 = p[3 * stride4 + o4];
        float4 s;
        s.x = (v0.x + v1.x) + (v2.x + v3.x);
        s.y = (v0.y + v1.y) + (v2.y + v3.y);
        s.z = (v0.z + v1.z) + (v2.z + v3.z);
        s.w = (v0.w + v1.w) + (v2.w + v3.w);
        if (b >= 1) {
            float4 nv = ((const float4*)g_nacc)[o4];
            s.x += nv.x; s.y += nv.y; s.z += nv.z; s.w += nv.w;
        }
        if (b >= 2) {
            float4 uv = ((const float4*)g_upd)[o4];
            s.x += uv.x; s.y += uv.y; s.z += uv.z; s.w += uv.w;
        }
        z[0] = s.x * SC; z[1] = s.y * SC; z[2] = s.z * SC; z[3] = s.w * SC;
    }
    __syncthreads();

    // Recurrence. Producer of step t: lane t>>2, component t&3.
    // Software pipeline: w for step t loaded during step t-1's chain.
    const float* wrow = ws + lane * 4;   // + t*132
    float4 w = *(const float4*)(wrow);   // t = 0
    for (int t0 = 0; t0 < 128; t0 += 4) {
#pragma unroll
        for (int tk = 0; tk < 4; tk++) {
            int t = t0 + tk;
            float4 wn = *(const float4*)(wrow + ((t + 1) & 127) * 132);

            float e;  asm("ex2.approx.f32 %0, %1;" : "=f"(e) : "f"(z[tk]));
            float d = e + 1.0f;
            float r;  asm("rcp.approx.f32 %0, %1;" : "=f"(r) : "f"(d));
            float hv = fmaf(-2.0f, r, 1.0f);

            float h = __shfl_sync(0xffffffffu, hv, t >> 2);

            z[0] = fmaf(h, w.x, z[0]);
            z[1] = fmaf(h, w.y, z[1]);
            z[2] = fmaf(h, w.z, z[2]);
            z[3] = fmaf(h, w.w, z[3]);
            w = wn;
        }
    }

    // Finalize own h (z[c] final after own step; later tri entries are 0).
    float h4[4];
#pragma unroll
    for (int c = 0; c < 4; c++) {
        float e;  asm("ex2.approx.f32 %0, %1;" : "=f"(e) : "f"(z[c]));
        float d = e + 1.0f;
        float r;  asm("rcp.approx.f32 %0, %1;" : "=f"(r) : "f"(d));
        h4[c] = fmaf(-2.0f, r, 1.0f);
    }

    if (b == NBLK - 1) {
        float4 o;
        o.x = 1.0f / (1.0f + __expf(-h4[0]));
        o.y = 1.0f / (1.0f + __expf(-h4[1]));
        o.z = 1.0f / (1.0f + __expf(-h4[2]));
        o.w = 1.0f / (1.0f + __expf(-h4[3]));
        *(float4*)(out + (size_t)row * OUT_N + 4 * lane) = o;
        return;
    }

    // Publish h: smem for fused near-update; gmem for U(b) (event-ordered).
    *(float4*)&hs[wid * 128 + 4 * lane] = *(float4*)h4;
    if (b <= NBLK - 3)
        *(float4*)(g_hall + (size_t)row * NN + j0 + 4 * lane) = *(float4*)h4;
    __syncthreads();

    // Near-update (all from smem): g_nacc[row][block b+1] = h_row @ Wn^T.
    {
        const float* hrow = hs + wid * 128;
        float acc0 = 0.f, acc1 = 0.f, acc2 = 0.f, acc3 = 0.f;
#pragma unroll 8
        for (int t = 0; t < 128; t++) {
            float hv = hrow[t];
            float4 wv = *(const float4*)&nearw[t * 128 + 4 * lane];
            acc0 = fmaf(hv, wv.x, acc0);
            acc1 = fmaf(hv, wv.y, acc1);
            acc2 = fmaf(hv, wv.z, acc2);
            acc3 = fmaf(hv, wv.w, acc3);
        }
        float4 a; a.x = acc0; a.y = acc1; a.z = acc2; a.w = acc3;
        *(float4*)(g_nacc + (size_t)row * NN + j0 + KB + 4 * lane) = a;
    }
}

// ---------------------------------------------------------------------------
// Host: event-only ordering, chunked preA so seq(0) starts after ~25us.
//  s3: prep -> preA[blocks 0-1] evP0 -> preA[2-7] evP1 -> preA[8-32] evP2
//  s2: zero g_upd; then U(b) after evS[b]
//  0 : seq(b) waits {evP0@b0, evP1@b2, evP2@b8, evU[b-2]}; records evS[b]
// ---------------------------------------------------------------------------
extern "C" void kernel_launch(void* const* d_in, const int* in_sizes, int n_in,
                              void* d_out, int out_size)
{
    const float* x = (const float*)d_in[0];   // [512][1024]
    const float* W = (const float*)d_in[1];   // [4224][5248]
    float* out = (float*)d_out;               // [512][128]
    (void)in_sizes; (void)n_in; (void)out_size;

    static bool inited = false;
    static cudaStream_t s2, s3;
    static cudaEvent_t evFork, evP0, evP1, evP2, evE2;
    static cudaEvent_t evS[NBLK], evU[NBLK];
    if (!inited) {
        cudaStreamCreateWithFlags(&s2, cudaStreamNonBlocking);
        cudaStreamCreateWithFlags(&s3, cudaStreamNonBlocking);
        cudaEventCreateWithFlags(&evFork, cudaEventDisableTiming);
        cudaEventCreateWithFlags(&evP0,   cudaEventDisableTiming);
        cudaEventCreateWithFlags(&evP1,   cudaEventDisableTiming);
        cudaEventCreateWithFlags(&evP2,   cudaEventDisableTiming);
        cudaEventCreateWithFlags(&evE2,   cudaEventDisableTiming);
        for (int i = 0; i < NBLK; i++) {
            cudaEventCreateWithFlags(&evS[i], cudaEventDisableTiming);
            cudaEventCreateWithFlags(&evU[i], cudaEventDisableTiming);
        }
        cudaFuncSetAttribute(seq_kernel,
                             cudaFuncAttributeMaxDynamicSharedMemorySize,
                             (128 * 132 + 128 * 128 + 16 * 128) * 4);
        inited = true;
    }

    const int SEQ_SMEM = (128 * 132 + 128 * 128 + 16 * 128) * 4;

    cudaEventRecord(evFork, 0);
    cudaStreamWaitEvent(s2, evFork, 0);
    cudaStreamWaitEvent(s3, evFork, 0);

    // s3: prep tiles, then chunked split-K preA.
    prep_kernel<<<2 * NBLK - 1, 256, 0, s3>>>(W);
    prea_kernel<<<dim3(4, 4, 4),  256, 0, s3>>>(x, W, 0);   // blocks 0-1
    cudaEventRecord(evP0, s3);
    prea_kernel<<<dim3(4, 12, 4), 256, 0, s3>>>(x, W, 4);   // blocks 2-7
    cudaEventRecord(evP1, s3);
    prea_kernel<<<dim3(4, 50, 4), 256, 0, s3>>>(x, W, 16);  // blocks 8-32
    cudaEventRecord(evP2, s3);

    // s2: zero the far accumulator (U(0) is serialized behind it on s2).
    zero_upd_kernel<<<2112, 256, 0, s2>>>();

    // stream 0: the pipeline.
    for (int b = 0; b < NBLK; b++) {
        if (b == 0) cudaStreamWaitEvent(0, evP0, 0);
        if (b == 2) cudaStreamWaitEvent(0, evP1, 0);
        if (b == 8) cudaStreamWaitEvent(0, evP2, 0);
        if (b >= 2) cudaStreamWaitEvent(0, evU[b - 2], 0);

        seq_kernel<<<32, 512, SEQ_SMEM, 0>>>(out, b);

        if (b <= NBLK - 3) {
            cudaEventRecord(evS[b], 0);
            cudaStreamWaitEvent(s2, evS[b], 0);
            int jb = (b + 2) * KB;
            upd_kernel<<<dim3(4, (NN - jb) / 64), 256, 0, s2>>>(W, b);
            cudaEventRecord(evU[b], s2);
        }
    }
    cudaEventRecord(evE2, s2);
    cudaStreamWaitEvent(0, evE2, 0);
}